// round 15
// baseline (speedup 1.0000x reference)
#include <cuda_runtime.h>

#define B_ROWS 8192
#define P_ROWS 1024
#define D_DIM  256
#define NPART  32          // producer blocks, 32 proto rows each
#define GRID   512         // 256 thr, 4/SM resident -> barrier-safe
#define ROWS_PER_BLK (B_ROWS / GRID)   // 16: 8 warps * 2 rows

// Device-global scratch (allocation-free rule), zero-initialized at load.
__device__ float g_partial[NPART * D_DIM];   // per-producer column sums
__device__ float g_p2[NPART];                // per-producer sum of squares
__device__ float g_m2[D_DIM];                // FINAL 2*mean_p proto[:,d]
__device__ float g_c;                        // FINAL mean_p ||p||^2
__device__ unsigned int g_count = 0;         // producer arrivals (32)
__device__ unsigned int g_ready = 0;         // m2/c published flag
__device__ unsigned int g_done  = 0;         // exit counter (replay reset)

__device__ __forceinline__ unsigned int ld_acq_u32(const unsigned int* p) {
    unsigned int v;
    asm volatile("ld.acquire.gpu.global.u32 %0, [%1];" : "=r"(v) : "l"(p) : "memory");
    return v;
}
__device__ __forceinline__ void st_rel_u32(unsigned int* p, unsigned int v) {
    asm volatile("st.release.gpu.global.u32 [%0], %1;" :: "l"(p), "r"(v) : "memory");
}

__global__ void __launch_bounds__(256, 4)
som_fused(const float* __restrict__ x,
          const float* __restrict__ proto,
          float* __restrict__ out) {
    const int tid  = threadIdx.x;
    const int lane = tid & 31;
    const int warp = tid >> 5;
    const int blk  = blockIdx.x;

    __shared__ __align__(16) float sm_grp[4 * D_DIM];
    __shared__ float sm_p2g[8];
    __shared__ unsigned int sm_role;

    // x addressing: lane L holds d[4L,4L+4) and d[128+4L,...) of rows row0,row0+1
    // -> every LDG.128 is a fully coalesced 512B warp op.
    const int row0 = blk * ROWS_PER_BLK + warp * 2;
    const float* r0p = x + row0 * D_DIM + lane * 4;
    const float* r1p = r0p + D_DIM;
    float4 a0, a1, b0, b1;

    if (blk < NPART) {
        // ---- Producer: proto loads FIRST (critical path to the barrier) ------
        const int c4   = tid & 63;           // float4 column group
        const int g    = tid >> 6;           // 4 row-groups of 8 rows
        const int prow = blk * (P_ROWS / NPART) + g * 8;

        float4 s = make_float4(0.f, 0.f, 0.f, 0.f);
        float sq = 0.f;
#pragma unroll
        for (int r = 0; r < 8; ++r) {        // 8 independent LDG.128 (one round)
            float4 v = *reinterpret_cast<const float4*>(
                proto + (prow + r) * D_DIM + c4 * 4);
            s.x += v.x; s.y += v.y; s.z += v.z; s.w += v.w;
            sq  += v.x * v.x + v.y * v.y + v.z * v.z + v.w * v.w;
        }
        *reinterpret_cast<float4*>(&sm_grp[g * D_DIM + c4 * 4]) = s;

#pragma unroll
        for (int o = 16; o > 0; o >>= 1)
            sq += __shfl_down_sync(0xFFFFFFFFu, sq, o);
        if (lane == 0) sm_p2g[warp] = sq;
        __syncthreads();

        g_partial[blk * D_DIM + tid] =
            sm_grp[tid] + sm_grp[D_DIM + tid] +
            sm_grp[2 * D_DIM + tid] + sm_grp[3 * D_DIM + tid];
        if (tid == 0) {
            float p2 = 0.f;
#pragma unroll
            for (int i = 0; i < 8; ++i) p2 += sm_p2g[i];
            g_p2[blk] = p2;
        }

        // R6 race fix: EVERY thread fences its own global store, then arrive.
        __threadfence();
        __syncthreads();
        if (tid == 0) {
            unsigned int old = atomicAdd(&g_count, 1u);
            sm_role = (old == NPART - 1) ? 1u : 0u;
        }
        __syncthreads();

        if (sm_role) {
            // ---- Last producer: combine -> FINAL m2/c, publish flag ----------
            __threadfence();                 // acquire side of all arrivals
            float s2 = 0.f;
#pragma unroll
            for (int i = 0; i < NPART; ++i)  // 32 L2-hit loads, MLP=32
                s2 += __ldcg(&g_partial[i * D_DIM + tid]);
            g_m2[tid] = s2 * (2.0f / (float)P_ROWS);
            if (warp == 0) {
                float v = __ldcg(&g_p2[lane]);
#pragma unroll
                for (int o = 16; o > 0; o >>= 1)
                    v += __shfl_down_sync(0xFFFFFFFFu, v, o);
                if (lane == 0) g_c = v * (1.0f / (float)P_ROWS);
            }
            __threadfence();                 // m2/c visible before the flag
            __syncthreads();
            if (tid == 0) st_rel_u32(&g_ready, 1u);
        }

        // x loads after arrival: latency hides under the spin below.
        a0 = *reinterpret_cast<const float4*>(r0p);
        a1 = *reinterpret_cast<const float4*>(r0p + 128);
        b0 = *reinterpret_cast<const float4*>(r1p);
        b1 = *reinterpret_cast<const float4*>(r1p + 128);
    } else {
        // ---- Consumer: x loads are the FIRST memory ops (R14 win) ------------
        a0 = *reinterpret_cast<const float4*>(r0p);
        a1 = *reinterpret_cast<const float4*>(r0p + 128);
        b0 = *reinterpret_cast<const float4*>(r1p);
        b1 = *reinterpret_cast<const float4*>(r1p + 128);
    }

    // ---- Barrier: spin on the published flag ---------------------------------
    if (tid == 0) {
        while (ld_acq_u32(&g_ready) == 0u) { }
    }
    __syncthreads();

    // ---- Minimal post-release tail: 1 L2 round for m2/c, FMA, reduce, store --
    const float4 m0 = __ldcg(reinterpret_cast<const float4*>(&g_m2[lane * 4]));
    const float4 m1 = __ldcg(reinterpret_cast<const float4*>(&g_m2[128 + lane * 4]));
    const float  c  = __ldcg(&g_c);

    float acc0, acc1;
    acc0  = a0.x * (a0.x - m0.x);  acc1  = b0.x * (b0.x - m0.x);
    acc0 += a0.y * (a0.y - m0.y);  acc1 += b0.y * (b0.y - m0.y);
    acc0 += a0.z * (a0.z - m0.z);  acc1 += b0.z * (b0.z - m0.z);
    acc0 += a0.w * (a0.w - m0.w);  acc1 += b0.w * (b0.w - m0.w);
    acc0 += a1.x * (a1.x - m1.x);  acc1 += b1.x * (b1.x - m1.x);
    acc0 += a1.y * (a1.y - m1.y);  acc1 += b1.y * (b1.y - m1.y);
    acc0 += a1.z * (a1.z - m1.z);  acc1 += b1.z * (b1.z - m1.z);
    acc0 += a1.w * (a1.w - m1.w);  acc1 += b1.w * (b1.w - m1.w);

#pragma unroll
    for (int o = 16; o > 0; o >>= 1) {
        acc0 += __shfl_down_sync(0xFFFFFFFFu, acc0, o);
        acc1 += __shfl_down_sync(0xFFFFFFFFu, acc1, o);
    }
    if (lane == 0) {
        out[row0]     = acc0 + c;
        out[row0 + 1] = acc1 + c;
    }

    // ---- Replay-state reset (measured harmless) ------------------------------
    __syncthreads();
    if (tid == 0) {
        unsigned int d = atomicAdd(&g_done, 1u);
        if (d == GRID - 1) {                 // last block out resets everything
            g_count = 0;
            g_ready = 0;
            g_done  = 0;
            __threadfence();
        }
    }
}

extern "C" void kernel_launch(void* const* d_in, const int* in_sizes, int n_in,
                              void* d_out, int out_size) {
    const float* x     = (const float*)d_in[0];  // (8192, 256) float32
    const float* proto = (const float*)d_in[1];  // (1024, 256) float32
    float* out = (float*)d_out;                  // (8192,) float32

    som_fused<<<GRID, 256>>>(x, proto, out);
}

// round 16
// speedup vs baseline: 1.1905x; 1.1905x over previous
#include <cuda_runtime.h>

#define B_ROWS 8192
#define P_ROWS 1024
#define D_DIM  256
#define NPART  64          // producer blocks, 16 proto rows each (R14 config)
#define NCTR   4           // split arrival counters (different L2 lines)
#define GRID   512         // 256 thr, 4/SM resident -> barrier-safe
#define ROWS_PER_BLK (B_ROWS / GRID)   // 16: 8 warps * 2 rows

// Device-global scratch (allocation-free rule), zero-initialized at load.
__device__ float g_partial[NPART * D_DIM];      // per-producer column sums
__device__ float g_p2[NPART];                   // per-producer sum of squares
__device__ unsigned int g_count[NCTR * 32];     // 4 counters, 128B apart
__device__ unsigned int g_done = 0;             // exit counter (replay reset)

__device__ __forceinline__ unsigned int ld_acq_u32(const unsigned int* p) {
    unsigned int v;
    asm volatile("ld.acquire.gpu.global.u32 %0, [%1];" : "=r"(v) : "l"(p) : "memory");
    return v;
}

__global__ void __launch_bounds__(256, 4)
som_fused(const float* __restrict__ x,
          const float* __restrict__ proto,
          float* __restrict__ out) {
    const int tid  = threadIdx.x;
    const int lane = tid & 31;
    const int warp = tid >> 5;
    const int blk  = blockIdx.x;

    __shared__ __align__(16) float sm_grp[4 * D_DIM];  // row-group partials
    __shared__ __align__(16) float sm_m2[D_DIM];       // combined 2*mean vector
    __shared__ float sm_p2g[8];
    __shared__ float sm_c;

    // x addressing: lane L holds d[4L,4L+4) and d[128+4L,...) of rows row0,row0+1
    // -> every LDG.128 is a fully coalesced 512B warp op.
    const int row0 = blk * ROWS_PER_BLK + warp * 2;
    const float* r0p = x + row0 * D_DIM + lane * 4;
    const float* r1p = r0p + D_DIM;
    float4 a0, a1, b0, b1;

    if (blk < NPART) {
        // ---- Producer: proto loads FIRST (critical path to the barrier) ------
        const int c4   = tid & 63;           // float4 column group
        const int g    = tid >> 6;           // 4 row-groups of 4 rows
        const int prow = blk * (P_ROWS / NPART) + g * 4;

        float4 s = make_float4(0.f, 0.f, 0.f, 0.f);
        float sq = 0.f;
#pragma unroll
        for (int r = 0; r < 4; ++r) {        // 4 independent LDG.128
            float4 v = *reinterpret_cast<const float4*>(
                proto + (prow + r) * D_DIM + c4 * 4);
            s.x += v.x; s.y += v.y; s.z += v.z; s.w += v.w;
            sq  += v.x * v.x + v.y * v.y + v.z * v.z + v.w * v.w;
        }
        *reinterpret_cast<float4*>(&sm_grp[g * D_DIM + c4 * 4]) = s;

#pragma unroll
        for (int o = 16; o > 0; o >>= 1)
            sq += __shfl_down_sync(0xFFFFFFFFu, sq, o);
        if (lane == 0) sm_p2g[warp] = sq;
        __syncthreads();

        g_partial[blk * D_DIM + tid] =
            sm_grp[tid] + sm_grp[D_DIM + tid] +
            sm_grp[2 * D_DIM + tid] + sm_grp[3 * D_DIM + tid];
        if (tid == 0) {
            float p2 = 0.f;
#pragma unroll
            for (int i = 0; i < 8; ++i) p2 += sm_p2g[i];
            g_p2[blk] = p2;
        }

        // R6 race fix: EVERY thread fences its own global store, then arrive.
        // Arrival spread over 4 counters on distinct L2 lines: 16-deep
        // serialization per line instead of 64-deep on one.
        __threadfence();
        __syncthreads();
        if (tid == 0)
            atomicAdd(&g_count[(blk & (NCTR - 1)) * 32], 1u);

        // x loads after arrival: latency hides under the spin below.
        a0 = *reinterpret_cast<const float4*>(r0p);
        a1 = *reinterpret_cast<const float4*>(r0p + 128);
        b0 = *reinterpret_cast<const float4*>(r1p);
        b1 = *reinterpret_cast<const float4*>(r1p + 128);
    } else {
        // ---- Consumer: x loads are the FIRST memory ops (R14 win) ------------
        a0 = *reinterpret_cast<const float4*>(r0p);
        a1 = *reinterpret_cast<const float4*>(r0p + 128);
        b0 = *reinterpret_cast<const float4*>(r1p);
        b1 = *reinterpret_cast<const float4*>(r1p + 128);
    }

    // ---- Grid barrier: spin on the SUM of the 4 counters (MLP=4 per iter) ----
    if (tid == 0) {
        for (;;) {
            unsigned int s = ld_acq_u32(&g_count[0])
                           + ld_acq_u32(&g_count[32])
                           + ld_acq_u32(&g_count[64])
                           + ld_acq_u32(&g_count[96]);
            if (s >= NPART) break;
        }
    }
    __syncthreads();

    // ---- Combine (every block, redundant; 66KB L2-resident, proven cheap) ----
    {
        const int c4 = tid & 63;
        const int g  = tid >> 6;
        float4 s = make_float4(0.f, 0.f, 0.f, 0.f);
#pragma unroll
        for (int i = 0; i < NPART / 4; ++i) {   // 16 partial rows per group
            float4 v = __ldcg(reinterpret_cast<const float4*>(
                &g_partial[(g * (NPART / 4) + i) * D_DIM + c4 * 4]));
            s.x += v.x; s.y += v.y; s.z += v.z; s.w += v.w;
        }
        *reinterpret_cast<float4*>(&sm_grp[g * D_DIM + c4 * 4]) = s;

        if (warp == 0) {                     // all 32 lanes participate (R5 fix)
            float v = __ldcg(&g_p2[lane]) + __ldcg(&g_p2[lane + 32]);
#pragma unroll
            for (int o = 16; o > 0; o >>= 1)
                v += __shfl_down_sync(0xFFFFFFFFu, v, o);
            if (lane == 0) sm_c = v * (1.0f / (float)P_ROWS);
        }
        __syncthreads();

        float m = sm_grp[tid] + sm_grp[D_DIM + tid] +
                  sm_grp[2 * D_DIM + tid] + sm_grp[3 * D_DIM + tid];
        sm_m2[tid] = m * (2.0f / (float)P_ROWS);
        __syncthreads();
    }

    // ---- Phase 3: compute from registers (x already in-flight/arrived) -------
    const float  c  = sm_c;
    const float4 m0 = *reinterpret_cast<const float4*>(&sm_m2[lane * 4]);
    const float4 m1 = *reinterpret_cast<const float4*>(&sm_m2[128 + lane * 4]);

    float acc0, acc1;
    acc0  = a0.x * (a0.x - m0.x);  acc1  = b0.x * (b0.x - m0.x);
    acc0 += a0.y * (a0.y - m0.y);  acc1 += b0.y * (b0.y - m0.y);
    acc0 += a0.z * (a0.z - m0.z);  acc1 += b0.z * (b0.z - m0.z);
    acc0 += a0.w * (a0.w - m0.w);  acc1 += b0.w * (b0.w - m0.w);
    acc0 += a1.x * (a1.x - m1.x);  acc1 += b1.x * (b1.x - m1.x);
    acc0 += a1.y * (a1.y - m1.y);  acc1 += b1.y * (b1.y - m1.y);
    acc0 += a1.z * (a1.z - m1.z);  acc1 += b1.z * (b1.z - m1.z);
    acc0 += a1.w * (a1.w - m1.w);  acc1 += b1.w * (b1.w - m1.w);

#pragma unroll
    for (int o = 16; o > 0; o >>= 1) {
        acc0 += __shfl_down_sync(0xFFFFFFFFu, acc0, o);
        acc1 += __shfl_down_sync(0xFFFFFFFFu, acc1, o);
    }
    if (lane == 0) {
        out[row0]     = acc0 + c;
        out[row0 + 1] = acc1 + c;
    }

    // ---- Replay-state reset (measured harmless) ------------------------------
    __syncthreads();
    if (tid == 0) {
        unsigned int d = atomicAdd(&g_done, 1u);
        if (d == GRID - 1) {                 // last block out resets everything
            g_count[0]  = 0;
            g_count[32] = 0;
            g_count[64] = 0;
            g_count[96] = 0;
            g_done = 0;
            __threadfence();
        }
    }
}

extern "C" void kernel_launch(void* const* d_in, const int* in_sizes, int n_in,
                              void* d_out, int out_size) {
    const float* x     = (const float*)d_in[0];  // (8192, 256) float32
    const float* proto = (const float*)d_in[1];  // (1024, 256) float32
    float* out = (float*)d_out;                  // (8192,) float32

    som_fused<<<GRID, 256>>>(x, proto, out);
}